// round 16
// baseline (speedup 1.0000x reference)
#include <cuda_runtime.h>
#include <cuda_fp16.h>
#include <cstdint>
#include <mma.h>

using namespace nvcuda;

#define EPSF 0.1f
constexpr int BB = 16, NN = 1024, DD = 2048;
constexpr int NITER_RUN = 4;       // truncation ~2e-4 bound; quantization floor 6.7e-5
#define LOGSCALE 6.2383246250395f  // ln(512)
#define LOG2E    1.44269504089f

// ---------------- static scratch (no allocations allowed) ----------------
__device__ __align__(128) __half g_Tn[(size_t)BB * NN * DD];          // normalized teacher fp16
__device__ __align__(128) __half g_Sn[(size_t)BB * NN * DD];          // normalized student fp16
__device__ __align__(128) unsigned char g_K [(size_t)BB * NN * NN];   // K_hat = 512*exp(-C/eps), e4m3
__device__ __align__(128) unsigned char g_S8[(size_t)BB * NN * NN];   // 64*(C_tilde - 0.5), e4m3
__device__ float    g_acc[BB * NITER_RUN * NN];                       // per-iteration column accumulators
__device__ unsigned g_bar[BB];
__device__ float    g_partial[128];
__device__ unsigned g_done;

// ---------------- fp8 / math helpers ----------------
__device__ __forceinline__ __half2 fp8x2_to_half2(unsigned short v) {
    unsigned r;
    asm("cvt.rn.f16x2.e4m3x2 %0, %1;" : "=r"(r) : "h"(v));
    return *reinterpret_cast<__half2*>(&r);
}
__device__ __forceinline__ unsigned short floats_to_fp8x2(float lo, float hi) {
    unsigned short r;
    asm("cvt.rn.satfinite.e4m3x2.f32 %0, %1, %2;" : "=h"(r) : "f"(hi), "f"(lo));
    return r;
}
// FFMA-only exp2: floor split + endpoint-exact cubic (rel err ~1e-4). No MUFU.
__device__ __forceinline__ float fast_exp2(float y) {
    float fn = floorf(y);
    float f  = y - fn;
    float m  = fmaf(f, fmaf(f, fmaf(f, 0.0790209f, 0.2252015f), 0.6957776f), 1.0f);
    float sc = __int_as_float(((int)fn + 127) << 23);
    return m * sc;
}
__device__ __forceinline__ unsigned sptr32(const void* p) {
    return (unsigned)__cvta_generic_to_shared(p);
}
__device__ __forceinline__ void cp16(void* s, const void* g) {
    asm volatile("cp.async.cg.shared.global [%0], [%1], 16;\n" :: "r"(sptr32(s)), "l"(g));
}
__device__ __forceinline__ void cp_commit() { asm volatile("cp.async.commit_group;\n"); }
__device__ __forceinline__ void cp_wait1()  { asm volatile("cp.async.wait_group 1;\n"); }
__device__ __forceinline__ void cp_wait0()  { asm volatile("cp.async.wait_group 0;\n"); }
__device__ __forceinline__ unsigned ld_acq(unsigned* p) {
    unsigned v;
    asm volatile("ld.acquire.gpu.u32 %0, [%1];" : "=r"(v) : "l"(p) : "memory");
    return v;
}

// ---------------- normalization (+ state init), 4 batches per launch ----------------
__global__ void __launch_bounds__(256) norm_kernel(const float* __restrict__ teacher,
                                                   const float* __restrict__ student, int b0) {
    if (b0 == 0) {
        if (blockIdx.x < 64) {   // zero g_acc: 64 * 256 * 4 = 65536 floats
            float4 z = make_float4(0.f, 0.f, 0.f, 0.f);
            ((float4*)g_acc)[blockIdx.x * 256 + threadIdx.x] = z;
        }
        if (blockIdx.x == 64) {
            if (threadIdx.x < BB) g_bar[threadIdx.x] = 0u;
            if (threadIdx.x == 0) g_done = 0u;
        }
    }

    int idx  = blockIdx.x * 8 + (threadIdx.x >> 5);   // 4 batches x 2048 rows
    int lane = threadIdx.x & 31;
    int batch = b0 + (idx >> 11);
    int r = idx & 2047;
    const float* x;
    __half* o;
    if (r < NN) { size_t gr = (size_t)batch * NN + r;        x = teacher + gr * DD; o = g_Tn + gr * DD; }
    else        { size_t gr = (size_t)batch * NN + (r - NN); x = student + gr * DD; o = g_Sn + gr * DD; }

    const float4* p = (const float4*)x;
    float s = 0.f;
    #pragma unroll 4
    for (int t = lane; t < DD / 4; t += 32) {
        float4 q = __ldcs(p + t);
        s += q.x*q.x + q.y*q.y + q.z*q.z + q.w*q.w;
    }
    #pragma unroll
    for (int off = 16; off; off >>= 1) s += __shfl_xor_sync(0xffffffffu, s, off);
    float rn = 1.f / fmaxf(sqrtf(s), 1e-12f);

    __half2* oh = (__half2*)o;
    for (int t = lane; t < DD / 4; t += 32) {
        float4 q = __ldcs(p + t);
        oh[2*t]   = __floats2half2_rn(q.x*rn, q.y*rn);
        oh[2*t+1] = __floats2half2_rn(q.z*rn, q.w*rn);
    }
}

// ---------------- fp16 wmma GEMM (128x128 tile, K-slab 64 — R10-measured best) ----------------
constexpr int GTILE = 128, GKT = 64, GPITCH = 72;       // halves
constexpr int GSMEM_BYTES = 2 * 2 * GTILE * GPITCH * 2; // 73728

__global__ void __launch_bounds__(256) gemm_kernel(int b0) {
    extern __shared__ __align__(16) char smem_raw[];
    const int b  = b0 + blockIdx.z;
    const int i0 = blockIdx.y * GTILE;
    const int j0 = blockIdx.x * GTILE;

    __half* sA = (__half*)smem_raw;                 // [2][128*72]
    __half* sB = sA + 2 * GTILE * GPITCH;           // [2][128*72]

    const __half* A  = g_Tn + (size_t)b * NN * DD + (size_t)i0 * DD;
    const __half* Bm = g_Sn + (size_t)b * NN * DD + (size_t)j0 * DD;

    const int tid = threadIdx.x;
    const int wid = tid >> 5;
    const int wm  = wid & 3;   // 4 row-warps, 32 rows each
    const int wn  = wid >> 2;  // 2 col-warps, 64 cols each

    auto load_stage = [&](int stage, int kt) {
        int k0 = kt * GKT;
        #pragma unroll
        for (int x = tid; x < 1024; x += 256) {
            int r = x >> 3, c = x & 7;
            cp16(&sA[stage*GTILE*GPITCH + r*GPITCH + c*8], A  + (size_t)r*DD + k0 + c*8);
            cp16(&sB[stage*GTILE*GPITCH + r*GPITCH + c*8], Bm + (size_t)r*DD + k0 + c*8);
        }
        cp_commit();
    };

    wmma::fragment<wmma::accumulator, 16, 16, 16, float> acc[2][4];
    #pragma unroll
    for (int r = 0; r < 2; r++)
        #pragma unroll
        for (int c = 0; c < 4; c++) wmma::fill_fragment(acc[r][c], 0.0f);

    load_stage(0, 0);
    load_stage(1, 1);

    const int NK = DD / GKT; // 32
    for (int kt = 0; kt < NK; ++kt) {
        cp_wait1();
        __syncthreads();
        const int st = kt & 1;
        const __half* a  = &sA[st * GTILE * GPITCH];
        const __half* bp = &sB[st * GTILE * GPITCH];
        #pragma unroll
        for (int kk = 0; kk < GKT; kk += 16) {
            wmma::fragment<wmma::matrix_a, 16, 16, 16, __half, wmma::row_major> af[2];
            wmma::fragment<wmma::matrix_b, 16, 16, 16, __half, wmma::col_major> bf[4];
            wmma::load_matrix_sync(af[0], a + (wm*32      ) * GPITCH + kk, GPITCH);
            wmma::load_matrix_sync(af[1], a + (wm*32 + 16 ) * GPITCH + kk, GPITCH);
            #pragma unroll
            for (int c = 0; c < 4; c++)
                wmma::load_matrix_sync(bf[c], bp + (wn*64 + 16*c) * GPITCH + kk, GPITCH);
            #pragma unroll
            for (int r = 0; r < 2; r++)
                #pragma unroll
                for (int c = 0; c < 4; c++)
                    wmma::mma_sync(acc[r][c], af[r], bf[c], acc[r][c]);
        }
        __syncthreads();
        if (kt + 2 < NK) load_stage(kt & 1, kt + 2);
        else             cp_commit();
    }

    // ---------------- epilogue in two 64-row halves: K fp8 + S8 fp8 ----------------
    float*         sO = (float*)smem_raw;                       // 64 x 132 floats
    unsigned char* Kp = g_K  + (size_t)b * NN * NN;
    unsigned char* Sp = g_S8 + (size_t)b * NN * NN;

    const float Ac = 5.0f * LOG2E;
    const float Bc = (LOGSCALE - 5.0f) * LOG2E;

    #pragma unroll
    for (int h = 0; h < 2; ++h) {
        __syncthreads();
        if ((wm >> 1) == h) {
            int wmL = wm & 1;
            #pragma unroll
            for (int r = 0; r < 2; r++)
                #pragma unroll
                for (int c = 0; c < 4; c++)
                    wmma::store_matrix_sync(&sO[(wmL*32 + 16*r)*132 + wn*64 + 16*c],
                                            acc[r][c], 132, wmma::mem_row_major);
        }
        __syncthreads();
        for (int x = tid; x < 64 * 64; x += 256) {
            int i = x >> 6, jp = x & 63;
            float cos0 = sO[i*132 + 2*jp    ];
            float cos1 = sO[i*132 + 2*jp + 1];
            float y0 = fmaf(Ac, cos0, Bc), y1 = fmaf(Ac, cos1, Bc);
            float k0 = fast_exp2(y0),      k1 = fast_exp2(y1);
            unsigned short pk = floats_to_fp8x2(k0, k1);
            size_t base = (((size_t)(i0 + h*64 + i) * NN + j0) >> 1) + jp;
            ((unsigned short*)Kp)[base] = pk;
            // consistency-corrected cost: C~ = C - eps*ln(1+r), r = (K8-K)/K (validated)
            float2 kf = __half22float2(fp8x2_to_half2(pk));
            float r0 = (kf.x - k0) * fast_exp2(-y0);
            float r1 = (kf.y - k1) * fast_exp2(-y1);
            float Ct0 = (0.5f - 0.5f*cos0) - EPSF * (r0 - 0.5f*r0*r0);
            float Ct1 = (0.5f - 0.5f*cos1) - EPSF * (r1 - 0.5f*r1*r1);
            ((unsigned short*)Sp)[base] = floats_to_fp8x2((Ct0 - 0.5f) * 64.0f,
                                                          (Ct1 - 0.5f) * 64.0f);
        }
    }
}

// ---------------- smem-resident Sinkhorn: 8 CTAs/batch, each owns 128 rows of K ----------------
constexpr int SK_SMEM = 146432;
#define PHI_SCALE 512.0f

__global__ void __launch_bounds__(512) sinkhorn_kernel(float* __restrict__ out) {
    extern __shared__ __align__(16) char sm[];
    unsigned char* sK    = (unsigned char*)sm;
    float*         sphi  = (float*)(sm + 131072);
    __half2*       sg2   = (__half2*)(sm + 131584);
    float*         sgf   = (float*)(sm + 133632);
    __half2*       sphih = (__half2*)(sm + 137728);
    float*         sacc  = (float*)(sm + 138240);

    const int blk = blockIdx.x, b = blk >> 3, c = blk & 7;   // 8 CTAs per batch
    const int tid = threadIdx.x, lane = tid & 31, wid = tid >> 5;  // 16 warps

    const unsigned char* __restrict__ Kb = g_K  + (size_t)b * NN * NN + (size_t)c * 128 * NN;
    const unsigned char* __restrict__ Sb = g_S8 + (size_t)b * NN * NN + (size_t)c * 128 * NN;
    float* acc_base = g_acc + (size_t)b * NITER_RUN * NN;

    // one-time fill: 128KB of K into smem
    #pragma unroll
    for (int x = tid; x < 8192; x += 512)
        cp16(sK + x * 16, Kb + x * 16);
    cp_commit();
    cp_wait0();
    sg2[tid] = __float2half2_rn(1.0f);   // gamma = 1
    __syncthreads();

    for (int it = 0; it < NITER_RUN; ++it) {
        // ---- phi-pass: warp owns rows wid*8..+7; lane covers j = c8*128 + lane*4
        __half2 gr[16];
        #pragma unroll
        for (int c8 = 0; c8 < 8; c8++) {
            int gi = c8*64 + lane*2;
            gr[2*c8]   = sg2[gi];
            gr[2*c8+1] = sg2[gi + 1];
        }
        #pragma unroll
        for (int r8 = 0; r8 < 8; r8++) {
            int i = wid*8 + r8;
            float facc = 0.f;
            #pragma unroll
            for (int c8 = 0; c8 < 8; c8++) {
                unsigned u = *(unsigned*)(sK + i*1024 + c8*128 + lane*4);
                __half2 h0 = fp8x2_to_half2((unsigned short)(u & 0xFFFFu));
                __half2 h1 = fp8x2_to_half2((unsigned short)(u >> 16));
                __half2 p  = __hfma2(h1, gr[2*c8+1], __hmul2(h0, gr[2*c8]));
                float2 f = __half22float2(p);
                facc += f.x + f.y;
            }
            #pragma unroll
            for (int off = 16; off; off >>= 1) facc += __shfl_xor_sync(0xffffffffu, facc, off);
            if (!lane) {
                sphi[i]  = 1.f / facc;
                sphih[i] = __float2half2_rn(PHI_SCALE / facc);
            }
        }
        __syncthreads();

        // ---- gamma partials: warp = (row-half h, 128-col chunk); full-width b32 row reads
        {
            const int h = wid >> 3, chunk = wid & 7;
            const int j0 = chunk*128 + lane*4;
            float a0 = 0.f, a1 = 0.f, a2 = 0.f, a3 = 0.f;
            #pragma unroll 2
            for (int ib = 0; ib < 64; ib += 8) {
                __half2 s0 = __float2half2_rn(0.f), s1 = s0;
                #pragma unroll
                for (int k = 0; k < 8; k++) {
                    int i = h*64 + ib + k;
                    unsigned u = *(unsigned*)(sK + i*1024 + j0);
                    __half2 ph = sphih[i];
                    s0 = __hfma2(fp8x2_to_half2((unsigned short)(u & 0xFFFFu)), ph, s0);
                    s1 = __hfma2(fp8x2_to_half2((unsigned short)(u >> 16)),     ph, s1);
                }
                float2 f0 = __half22float2(s0), f1 = __half22float2(s1);
                a0 += f0.x; a1 += f0.y; a2 += f1.x; a3 += f1.y;
            }
            *(float4*)(sacc + h*1024 + j0) = make_float4(a0, a1, a2, a3);
        }
        __syncthreads();
        // combine halves, one REDG per column
        float* acc = acc_base + it * NN;
        {
            int j = 2 * tid;
            float v0 = (sacc[j]     + sacc[1024 + j]    ) * (1.0f / PHI_SCALE);
            float v1 = (sacc[j + 1] + sacc[1024 + j + 1]) * (1.0f / PHI_SCALE);
            atomicAdd(acc + j,     v0);
            atomicAdd(acc + j + 1, v1);
        }
        // ---- one global barrier per iteration (tid0 release, R10-proven)
        __syncthreads();
        if (tid == 0) {
            __threadfence();
            atomicAdd(&g_bar[b], 1u);
            unsigned t8 = 8u * (unsigned)(it + 1);
            while (ld_acq(&g_bar[b]) < t8) { }
        }
        __syncthreads();
        // ---- gamma = 1/acc, locally
        {
            int j = 2 * tid;
            float g0 = 1.f / __ldcg(acc + j), g1 = 1.f / __ldcg(acc + j + 1);
            sgf[j] = g0; sgf[j + 1] = g1;
            sg2[tid] = __floats2half2_rn(g0, g1);
        }
        __syncthreads();
    }

    // ---- loss: (1/N) sum_i phi_i sum_j gamma_j K_ij (0.5 + S8_ij/64) over own rows
    const __half2 hHalf = __float2half2_rn(0.5f);
    const __half2 hInv64 = __float2half2_rn(1.0f / 64.0f);
    float4 ga[8];
    #pragma unroll
    for (int c8 = 0; c8 < 8; c8++) ga[c8] = *(float4*)(sgf + c8*128 + lane*4);

    float accv = 0.f;
    #pragma unroll 1
    for (int r8 = 0; r8 < 8; ++r8) {
        int i = wid*8 + r8;
        const unsigned* Srow = (const unsigned*)(Sb + (size_t)i * 1024);
        float sum = 0.f;
        #pragma unroll
        for (int c8 = 0; c8 < 8; c8++) {
            unsigned us = __ldg(Srow + c8*32 + lane);
            unsigned uk = *(unsigned*)(sK + i*1024 + c8*128 + lane*4);
            __half2 ct0 = __hfma2(fp8x2_to_half2((unsigned short)(us & 0xFFFFu)), hInv64, hHalf);
            __half2 ct1 = __hfma2(fp8x2_to_half2((unsigned short)(us >> 16)),     hInv64, hHalf);
            __half2 t0 = __hmul2(fp8x2_to_half2((unsigned short)(uk & 0xFFFFu)), ct0);
            __half2 t1 = __hmul2(fp8x2_to_half2((unsigned short)(uk >> 16)),     ct1);
            float2 f0 = __half22float2(t0), f1 = __half22float2(t1);
            float4 g = ga[c8];
            sum = fmaf(f0.x, g.x, fmaf(f0.y, g.y, fmaf(f1.x, g.z, fmaf(f1.y, g.w, sum))));
        }
        #pragma unroll
        for (int off = 16; off; off >>= 1) sum += __shfl_xor_sync(0xffffffffu, sum, off);
        if (!lane) accv += sphi[i] * sum;
    }
    __shared__ float sred[16];
    __shared__ unsigned slast;
    __shared__ float s2[4];
    if (!lane) sred[wid] = accv;
    __syncthreads();
    if (tid == 0) {
        float t = 0.f;
        #pragma unroll
        for (int k2 = 0; k2 < 16; k2++) t += sred[k2];
        g_partial[blk] = t;
        __threadfence();
        slast = atomicAdd(&g_done, 1u);
    }
    __syncthreads();
    if (slast == 127) {   // fused finish
        if (tid < 128) {
            float v = g_partial[tid];
            #pragma unroll
            for (int off = 16; off; off >>= 1) v += __shfl_xor_sync(0xffffffffu, v, off);
            if (!lane) s2[tid >> 5] = v;
        }
        __syncthreads();
        if (tid == 0) out[0] = (s2[0] + s2[1] + s2[2] + s2[3]) * (1.0f / (BB * (float)NN));
    }
}

// ---------------- launch: norm chunks on one forked stream, gemm gated by events ----------------
extern "C" void kernel_launch(void* const* d_in, const int* in_sizes, int n_in,
                              void* d_out, int out_size) {
    const float* student = (const float*)d_in[0];   // [16,1024,2048]
    const float* teacher = (const float*)d_in[1];   // [16,1024,2048]

    cudaFuncSetAttribute(gemm_kernel,     cudaFuncAttributeMaxDynamicSharedMemorySize, GSMEM_BYTES);
    cudaFuncSetAttribute(sinkhorn_kernel, cudaFuncAttributeMaxDynamicSharedMemorySize, SK_SMEM);

    cudaStream_t s1;
    cudaStreamCreateWithFlags(&s1, cudaStreamNonBlocking);
    cudaEvent_t evS, evN[4];
    cudaEventCreateWithFlags(&evS, cudaEventDisableTiming);
    for (int c = 0; c < 4; c++) cudaEventCreateWithFlags(&evN[c], cudaEventDisableTiming);

    cudaEventRecord(evS, 0);
    cudaStreamWaitEvent(s1, evS, 0);
    for (int c = 0; c < 4; c++) {
        norm_kernel<<<1024, 256, 0, s1>>>(teacher, student, c * 4);
        cudaEventRecord(evN[c], s1);
    }
    for (int c = 0; c < 4; c++) {
        cudaStreamWaitEvent(0, evN[c], 0);
        gemm_kernel<<<dim3(8, 8, 4), 256, GSMEM_BYTES>>>(c * 4);
    }
    sinkhorn_kernel<<<128, 512, SK_SMEM>>>((float*)d_out);
}

// round 17
// speedup vs baseline: 1.0583x; 1.0583x over previous
#include <cuda_runtime.h>
#include <cuda_fp16.h>
#include <cstdint>
#include <mma.h>

using namespace nvcuda;

#define EPSF 0.1f
constexpr int BB = 16, NN = 1024, DD = 2048;
constexpr int NITER_RUN = 4;       // validated: rel_err 6.7e-5 at 4 iters (R16)
#define LOGSCALE 6.2383246250395f  // ln(512)
#define LOG2E    1.44269504089f

// ---------------- static scratch (no allocations allowed) ----------------
__device__ __align__(128) __half g_Tn[(size_t)BB * NN * DD];          // normalized teacher fp16
__device__ __align__(128) __half g_Sn[(size_t)BB * NN * DD];          // normalized student fp16
__device__ __align__(128) unsigned char g_K [(size_t)BB * NN * NN];   // K_hat = 512*exp(-C/eps), e4m3
__device__ __align__(128) __half g_L [(size_t)BB * NN * NN];          // L = K_hat8 * C_tilde, fp16
__device__ float    g_acc[BB * NITER_RUN * NN];                       // per-iteration column accumulators
__device__ unsigned g_bar[BB];
__device__ float    g_partial[128];
__device__ unsigned g_done;

// ---------------- fp8 / math helpers ----------------
__device__ __forceinline__ __half2 fp8x2_to_half2(unsigned short v) {
    unsigned r;
    asm("cvt.rn.f16x2.e4m3x2 %0, %1;" : "=r"(r) : "h"(v));
    return *reinterpret_cast<__half2*>(&r);
}
__device__ __forceinline__ unsigned short floats_to_fp8x2(float lo, float hi) {
    unsigned short r;
    asm("cvt.rn.satfinite.e4m3x2.f32 %0, %1, %2;" : "=h"(r) : "f"(hi), "f"(lo));
    return r;
}
// FFMA-only exp2: floor split + endpoint-exact cubic (rel err ~1e-4). No MUFU.
__device__ __forceinline__ float fast_exp2(float y) {
    float fn = floorf(y);
    float f  = y - fn;
    float m  = fmaf(f, fmaf(f, fmaf(f, 0.0790209f, 0.2252015f), 0.6957776f), 1.0f);
    float sc = __int_as_float(((int)fn + 127) << 23);
    return m * sc;
}
__device__ __forceinline__ unsigned sptr32(const void* p) {
    return (unsigned)__cvta_generic_to_shared(p);
}
__device__ __forceinline__ void cp16(void* s, const void* g) {
    asm volatile("cp.async.cg.shared.global [%0], [%1], 16;\n" :: "r"(sptr32(s)), "l"(g));
}
__device__ __forceinline__ void cp_commit() { asm volatile("cp.async.commit_group;\n"); }
__device__ __forceinline__ void cp_wait1()  { asm volatile("cp.async.wait_group 1;\n"); }
__device__ __forceinline__ void cp_wait0()  { asm volatile("cp.async.wait_group 0;\n"); }
__device__ __forceinline__ unsigned ld_acq(unsigned* p) {
    unsigned v;
    asm volatile("ld.acquire.gpu.u32 %0, [%1];" : "=r"(v) : "l"(p) : "memory");
    return v;
}

// ---------------- normalization (+ state init), 4 batches per launch ----------------
__global__ void __launch_bounds__(256) norm_kernel(const float* __restrict__ teacher,
                                                   const float* __restrict__ student, int b0) {
    if (b0 == 0) {
        if (blockIdx.x < 64) {   // zero g_acc: 64 * 256 * 4 = 65536 floats = BB*4*NN
            float4 z = make_float4(0.f, 0.f, 0.f, 0.f);
            ((float4*)g_acc)[blockIdx.x * 256 + threadIdx.x] = z;
        }
        if (blockIdx.x == 64) {
            if (threadIdx.x < BB) g_bar[threadIdx.x] = 0u;
            if (threadIdx.x == 0) g_done = 0u;
        }
    }

    int idx  = blockIdx.x * 8 + (threadIdx.x >> 5);   // 4 batches x 2048 rows
    int lane = threadIdx.x & 31;
    int batch = b0 + (idx >> 11);
    int r = idx & 2047;
    const float* x;
    __half* o;
    if (r < NN) { size_t gr = (size_t)batch * NN + r;        x = teacher + gr * DD; o = g_Tn + gr * DD; }
    else        { size_t gr = (size_t)batch * NN + (r - NN); x = student + gr * DD; o = g_Sn + gr * DD; }

    const float4* p = (const float4*)x;
    float s = 0.f;
    #pragma unroll 4
    for (int t = lane; t < DD / 4; t += 32) {
        float4 q = p[t];
        s += q.x*q.x + q.y*q.y + q.z*q.z + q.w*q.w;
    }
    #pragma unroll
    for (int off = 16; off; off >>= 1) s += __shfl_xor_sync(0xffffffffu, s, off);
    float rn = 1.f / fmaxf(sqrtf(s), 1e-12f);

    __half2* oh = (__half2*)o;
    for (int t = lane; t < DD / 4; t += 32) {
        float4 q = p[t];
        oh[2*t]   = __floats2half2_rn(q.x*rn, q.y*rn);
        oh[2*t+1] = __floats2half2_rn(q.z*rn, q.w*rn);
    }
}

// ---------------- fp16 wmma GEMM (K-slab 64): cos = Tn*Sn^T; fp8 K + consistent fp16 L ----------------
constexpr int GTILE = 128, GKT = 64, GPITCH = 72;       // halves
constexpr int GSMEM_BYTES = 2 * 2 * GTILE * GPITCH * 2; // 73728

__global__ void __launch_bounds__(256) gemm_kernel(int b0) {
    extern __shared__ __align__(16) char smem_raw[];
    const int b  = b0 + blockIdx.z;
    const int i0 = blockIdx.y * GTILE;
    const int j0 = blockIdx.x * GTILE;

    __half* sA = (__half*)smem_raw;                 // [2][128*72]
    __half* sB = sA + 2 * GTILE * GPITCH;           // [2][128*72]

    const __half* A  = g_Tn + (size_t)b * NN * DD + (size_t)i0 * DD;
    const __half* Bm = g_Sn + (size_t)b * NN * DD + (size_t)j0 * DD;

    const int tid = threadIdx.x;
    const int wid = tid >> 5;
    const int wm  = wid & 3;   // 4 row-warps, 32 rows each
    const int wn  = wid >> 2;  // 2 col-warps, 64 cols each

    auto load_stage = [&](int stage, int kt) {
        int k0 = kt * GKT;
        #pragma unroll
        for (int x = tid; x < 1024; x += 256) {
            int r = x >> 3, c = x & 7;
            cp16(&sA[stage*GTILE*GPITCH + r*GPITCH + c*8], A  + (size_t)r*DD + k0 + c*8);
            cp16(&sB[stage*GTILE*GPITCH + r*GPITCH + c*8], Bm + (size_t)r*DD + k0 + c*8);
        }
        cp_commit();
    };

    wmma::fragment<wmma::accumulator, 16, 16, 16, float> acc[2][4];
    #pragma unroll
    for (int r = 0; r < 2; r++)
        #pragma unroll
        for (int c = 0; c < 4; c++) wmma::fill_fragment(acc[r][c], 0.0f);

    load_stage(0, 0);
    load_stage(1, 1);

    const int NK = DD / GKT; // 32
    for (int kt = 0; kt < NK; ++kt) {
        cp_wait1();
        __syncthreads();
        const int st = kt & 1;
        const __half* a  = &sA[st * GTILE * GPITCH];
        const __half* bp = &sB[st * GTILE * GPITCH];
        #pragma unroll
        for (int kk = 0; kk < GKT; kk += 16) {
            wmma::fragment<wmma::matrix_a, 16, 16, 16, __half, wmma::row_major> af[2];
            wmma::fragment<wmma::matrix_b, 16, 16, 16, __half, wmma::col_major> bf[4];
            wmma::load_matrix_sync(af[0], a + (wm*32      ) * GPITCH + kk, GPITCH);
            wmma::load_matrix_sync(af[1], a + (wm*32 + 16 ) * GPITCH + kk, GPITCH);
            #pragma unroll
            for (int c = 0; c < 4; c++)
                wmma::load_matrix_sync(bf[c], bp + (wn*64 + 16*c) * GPITCH + kk, GPITCH);
            #pragma unroll
            for (int r = 0; r < 2; r++)
                #pragma unroll
                for (int c = 0; c < 4; c++)
                    wmma::mma_sync(acc[r][c], af[r], bf[c], acc[r][c]);
        }
        __syncthreads();
        if (kt + 2 < NK) load_stage(kt & 1, kt + 2);
        else             cp_commit();
    }

    // ---------------- epilogue in two 64-row halves ----------------
    float*         sO  = (float*)smem_raw;                       // 64 x 132 floats
    unsigned char* Kp  = g_K  + (size_t)b * NN * NN;
    __half*        Lp  = g_L  + (size_t)b * NN * NN;

    const float Ac = 5.0f * LOG2E;
    const float Bc = (LOGSCALE - 5.0f) * LOG2E;

    #pragma unroll
    for (int h = 0; h < 2; ++h) {
        __syncthreads();
        if ((wm >> 1) == h) {
            int wmL = wm & 1;
            #pragma unroll
            for (int r = 0; r < 2; r++)
                #pragma unroll
                for (int c = 0; c < 4; c++)
                    wmma::store_matrix_sync(&sO[(wmL*32 + 16*r)*132 + wn*64 + 16*c],
                                            acc[r][c], 132, wmma::mem_row_major);
        }
        __syncthreads();
        for (int x = tid; x < 64 * 64; x += 256) {
            int i = x >> 6, jp = x & 63;
            float cos0 = sO[i*132 + 2*jp    ];
            float cos1 = sO[i*132 + 2*jp + 1];
            float y0 = fmaf(Ac, cos0, Bc), y1 = fmaf(Ac, cos1, Bc);
            float k0 = fast_exp2(y0),      k1 = fast_exp2(y1);
            unsigned short pk = floats_to_fp8x2(k0, k1);
            ((unsigned short*)Kp)[(((size_t)(i0 + h*64 + i) * NN + j0) >> 1) + jp] = pk;
            // consistency-corrected cost: C~ = C - eps*ln(1+r), r = (K8-K)/K (validated R7/R8)
            float2 kf = __half22float2(fp8x2_to_half2(pk));
            float r0 = (kf.x - k0) * fast_exp2(-y0);
            float r1 = (kf.y - k1) * fast_exp2(-y1);
            float Ct0 = (0.5f - 0.5f*cos0) - EPSF * (r0 - 0.5f*r0*r0);
            float Ct1 = (0.5f - 0.5f*cos1) - EPSF * (r1 - 0.5f*r1*r1);
            ((__half2*)Lp)[(((size_t)(i0 + h*64 + i) * NN + j0) >> 1) + jp] =
                __floats2half2_rn(kf.x * Ct0, kf.y * Ct1);
        }
    }
}

// ---------------- smem-resident Sinkhorn: 8 CTAs/batch, each owns 128 rows of K ----------------
// smem: K 128x1024 fp8 @0 | phi f32[128] @131072 | gamma h2[512] @131584
//       gamma f32[1024] @133632 | phi*512 h2[128] @137728  -> total 138240 B
constexpr int SK_SMEM = 138240;
#define PHI_SCALE 512.0f

__global__ void __launch_bounds__(512) sinkhorn_kernel(float* __restrict__ out) {
    extern __shared__ __align__(16) char sm[];
    unsigned char* sK    = (unsigned char*)sm;
    float*         sphi  = (float*)(sm + 131072);
    __half2*       sg2   = (__half2*)(sm + 131584);
    float*         sgf   = (float*)(sm + 133632);
    __half2*       sphih = (__half2*)(sm + 137728);

    const int blk = blockIdx.x, b = blk >> 3, c = blk & 7;   // 8 CTAs per batch
    const int tid = threadIdx.x, lane = tid & 31, wid = tid >> 5;  // 16 warps

    const unsigned char* __restrict__ Kb = g_K + (size_t)b * NN * NN + (size_t)c * 128 * NN;
    const __half*        __restrict__ Lb = g_L + (size_t)b * NN * NN + (size_t)c * 128 * NN;
    float* acc_base = g_acc + (size_t)b * NITER_RUN * NN;

    // one-time fill: 128KB of K into smem
    #pragma unroll
    for (int x = tid; x < 8192; x += 512)
        cp16(sK + x * 16, Kb + x * 16);
    cp_commit();
    cp_wait0();
    sg2[tid] = __float2half2_rn(1.0f);   // gamma = 1
    __syncthreads();

    for (int it = 0; it < NITER_RUN; ++it) {
        // ---- phi-pass: warp owns rows wid*8..+7; lane covers j = c8*128 + lane*4
        __half2 gr[16];
        #pragma unroll
        for (int c8 = 0; c8 < 8; c8++) {
            int gi = c8*64 + lane*2;
            gr[2*c8]   = sg2[gi];
            gr[2*c8+1] = sg2[gi + 1];
        }
        #pragma unroll
        for (int r8 = 0; r8 < 8; r8++) {
            int i = wid*8 + r8;
            float facc = 0.f;
            #pragma unroll
            for (int c8 = 0; c8 < 8; c8++) {
                unsigned u = *(unsigned*)(sK + i*1024 + c8*128 + lane*4);
                __half2 h0 = fp8x2_to_half2((unsigned short)(u & 0xFFFFu));
                __half2 h1 = fp8x2_to_half2((unsigned short)(u >> 16));
                __half2 p  = __hfma2(h1, gr[2*c8+1], __hmul2(h0, gr[2*c8]));
                float2 f = __half22float2(p);
                facc += f.x + f.y;
            }
            #pragma unroll
            for (int off = 16; off; off >>= 1) facc += __shfl_xor_sync(0xffffffffu, facc, off);
            if (!lane) {
                sphi[i]  = 1.f / facc;
                sphih[i] = __float2half2_rn(PHI_SCALE / facc);   // scaled to stay normal in half
            }
        }
        __syncthreads();

        // ---- gamma partial pass: thread owns columns j0 = 2*tid, j0+1
        float* acc = acc_base + it * NN;
        {
            const int j0 = 2 * tid;
            float px = 0.f, py = 0.f;
            #pragma unroll 2
            for (int ib = 0; ib < 128; ib += 8) {
                __half2 h = __float2half2_rn(0.f);
                #pragma unroll
                for (int k = 0; k < 8; k++) {
                    int i = ib + k;
                    unsigned short u = *(unsigned short*)(sK + i*1024 + j0);
                    h = __hfma2(fp8x2_to_half2(u), sphih[i], h);
                }
                float2 f = __half22float2(h);
                px += f.x; py += f.y;
            }
            atomicAdd(acc + j0,     px * (1.0f / PHI_SCALE));
            atomicAdd(acc + j0 + 1, py * (1.0f / PHI_SCALE));
        }
        // ---- one global barrier per iteration (8 CTAs of this batch)
        __syncthreads();
        if (tid == 0) {
            __threadfence();
            atomicAdd(&g_bar[b], 1u);
            unsigned t8 = 8u * (unsigned)(it + 1);
            while (ld_acq(&g_bar[b]) < t8) { }
        }
        __syncthreads();
        // ---- gamma = 1/acc, locally
        {
            const int j0 = 2 * tid;
            float a0 = __ldcg(acc + j0), a1 = __ldcg(acc + j0 + 1);
            float gm0 = 1.f / a0, gm1 = 1.f / a1;
            sgf[j0] = gm0; sgf[j0 + 1] = gm1;
            sg2[tid] = __floats2half2_rn(gm0, gm1);
        }
        __syncthreads();
    }

    // ---- loss: (1/N) sum_i phi_i * sum_j gamma_j * L_ij over own rows
    float accv = 0.f;
    #pragma unroll 1
    for (int r8 = 0; r8 < 8; ++r8) {
        int i = wid*8 + r8;
        const uint4* rp = (const uint4*)(Lb + (size_t)i * NN);
        float sum = 0.f;
        #pragma unroll
        for (int c4 = 0; c4 < 4; c4++) {
            uint4 q = __ldg(rp + c4*32 + lane);        // 8 halves, j = c4*256 + lane*8
            int j = c4*256 + lane*8;
            const __half2* h2 = (const __half2*)&q;
            float4 wa = *(float4*)(sgf + j);
            float4 wb = *(float4*)(sgf + j + 4);
            float2 f;
            f = __half22float2(h2[0]); sum = fmaf(f.x, wa.x, fmaf(f.y, wa.y, sum));
            f = __half22float2(h2[1]); sum = fmaf(f.x, wa.z, fmaf(f.y, wa.w, sum));
            f = __half22float2(h2[2]); sum = fmaf(f.x, wb.x, fmaf(f.y, wb.y, sum));
            f = __half22float2(h2[3]); sum = fmaf(f.x, wb.z, fmaf(f.y, wb.w, sum));
        }
        #pragma unroll
        for (int off = 16; off; off >>= 1) sum += __shfl_xor_sync(0xffffffffu, sum, off);
        if (!lane) accv += sphi[i] * sum;
    }
    __shared__ float sred[16];
    __shared__ unsigned slast;
    __shared__ float s2[4];
    if (!lane) sred[wid] = accv;
    __syncthreads();
    if (tid == 0) {
        float t = 0.f;
        #pragma unroll
        for (int k2 = 0; k2 < 16; k2++) t += sred[k2];
        g_partial[blk] = t;
        __threadfence();
        slast = atomicAdd(&g_done, 1u);
    }
    __syncthreads();
    if (slast == 127) {   // fused finish: last CTA reduces all partials
        if (tid < 128) {
            float v = g_partial[tid];
            #pragma unroll
            for (int off = 16; off; off >>= 1) v += __shfl_xor_sync(0xffffffffu, v, off);
            if (!lane) s2[tid >> 5] = v;
        }
        __syncthreads();
        if (tid == 0) out[0] = (s2[0] + s2[1] + s2[2] + s2[3]) * (1.0f / (BB * (float)NN));
    }
}

// ---------------- launch: norm chunks on forked stream, gemm gated by events ----------------
extern "C" void kernel_launch(void* const* d_in, const int* in_sizes, int n_in,
                              void* d_out, int out_size) {
    const float* student = (const float*)d_in[0];   // [16,1024,2048]
    const float* teacher = (const float*)d_in[1];   // [16,1024,2048]

    cudaFuncSetAttribute(gemm_kernel,     cudaFuncAttributeMaxDynamicSharedMemorySize, GSMEM_BYTES);
    cudaFuncSetAttribute(sinkhorn_kernel, cudaFuncAttributeMaxDynamicSharedMemorySize, SK_SMEM);

    cudaStream_t s1;
    cudaStreamCreateWithFlags(&s1, cudaStreamNonBlocking);
    cudaEvent_t evS, evN[4];
    cudaEventCreateWithFlags(&evS, cudaEventDisableTiming);
    for (int c = 0; c < 4; c++) cudaEventCreateWithFlags(&evN[c], cudaEventDisableTiming);

    cudaEventRecord(evS, 0);
    cudaStreamWaitEvent(s1, evS, 0);
    for (int c = 0; c < 4; c++) {
        norm_kernel<<<1024, 256, 0, s1>>>(teacher, student, c * 4);
        cudaEventRecord(evN[c], s1);
    }
    for (int c = 0; c < 4; c++) {
        cudaStreamWaitEvent(0, evN[c], 0);
        gemm_kernel<<<dim3(8, 8, 4), 256, GSMEM_BYTES>>>(c * 4);
    }
    sinkhorn_kernel<<<128, 512, SK_SMEM>>>((float*)d_out);
}